// round 1
// baseline (speedup 1.0000x reference)
#include <cuda_runtime.h>

#define TM 32
#define NTHREADS 256

// h * Dormand-Prince A coefficients (h = 1/4)
__constant__ float c_HA[6][5] = {
    {0.f, 0.f, 0.f, 0.f, 0.f},
    {0.05f, 0.f, 0.f, 0.f, 0.f},
    {0.01875f, 0.05625f, 0.f, 0.f, 0.f},
    {0.24444444444444444f, -0.93333333333333333f, 0.88888888888888888f, 0.f, 0.f},
    {0.73814967232162782f, -2.89894833155005335f, 2.45572321290182902f, -0.07270233196159122f, 0.f},
    {0.71156881313131313f, -2.68939393939393939f, 2.22660567943586826f, 0.06960227272727273f, -0.06838282589193830f}
};
// h * b
__constant__ float c_HB[6] = {
    0.02278645833333333f, 0.f, 0.11230907457322552f,
    0.16276041666666666f, -0.08059404481132076f, 0.03273809523809524f
};

// GEMM: Y[ROWS][64] = W[ROWS][K] @ X[K][64], W from global (L2-resident),
// X/Y in shared. Double-buffered W k-panels in shared (wp = 2*256*9 floats).
template<int ROWS, int K>
__device__ __forceinline__ void gemm_layer(
    const float* __restrict__ W,
    const float* __restrict__ X,
    float* __restrict__ Y,
    float* __restrict__ wp,
    int tid)
{
    constexpr int NR = (ROWS == 256) ? 8 : 2;
    const int r0 = (tid >> 3) * NR;
    const int c0 = (tid & 7) * 8;
    float acc[NR][8];
#pragma unroll
    for (int i = 0; i < NR; i++)
#pragma unroll
        for (int j = 0; j < 8; j++) acc[i][j] = 0.f;

    const bool loader = (ROWS == 256) || (tid < 64);
    float4 nv0, nv1;
    if (loader) {
        const float4* src = reinterpret_cast<const float4*>(W + tid * K);
        nv0 = src[0]; nv1 = src[1];
        float* w0 = wp + tid * 9;
        w0[0] = nv0.x; w0[1] = nv0.y; w0[2] = nv0.z; w0[3] = nv0.w;
        w0[4] = nv1.x; w0[5] = nv1.y; w0[6] = nv1.z; w0[7] = nv1.w;
    }
    __syncthreads();
    int buf = 0;
#pragma unroll 1
    for (int kk = 0; kk < K; kk += 8) {
        // prefetch next panel (hidden under compute)
        if (kk + 8 < K && loader) {
            const float4* src = reinterpret_cast<const float4*>(W + tid * K + kk + 8);
            nv0 = src[0]; nv1 = src[1];
        }
        const float* wpb = wp + buf * (256 * 9);
#pragma unroll
        for (int k2 = 0; k2 < 8; k2++) {
            const float* xr = X + (kk + k2) * 64;
            float4 xa = *reinterpret_cast<const float4*>(xr + c0);
            float4 xb = *reinterpret_cast<const float4*>(xr + c0 + 4);
#pragma unroll
            for (int i = 0; i < NR; i++) {
                float w = wpb[(r0 + i) * 9 + k2];
                acc[i][0] += w * xa.x; acc[i][1] += w * xa.y;
                acc[i][2] += w * xa.z; acc[i][3] += w * xa.w;
                acc[i][4] += w * xb.x; acc[i][5] += w * xb.y;
                acc[i][6] += w * xb.z; acc[i][7] += w * xb.w;
            }
        }
        if (kk + 8 < K && loader) {
            float* w1 = wp + (buf ^ 1) * (256 * 9) + tid * 9;
            w1[0] = nv0.x; w1[1] = nv0.y; w1[2] = nv0.z; w1[3] = nv0.w;
            w1[4] = nv1.x; w1[5] = nv1.y; w1[6] = nv1.z; w1[7] = nv1.w;
        }
        __syncthreads();
        buf ^= 1;
    }
#pragma unroll
    for (int i = 0; i < NR; i++) {
        float* yr = Y + (r0 + i) * 64 + c0;
        *reinterpret_cast<float4*>(yr)     = make_float4(acc[i][0], acc[i][1], acc[i][2], acc[i][3]);
        *reinterpret_cast<float4*>(yr + 4) = make_float4(acc[i][4], acc[i][5], acc[i][6], acc[i][7]);
    }
}

// After a hidden-layer GEMM: cols 0..31 are pre-activations (add bias, tanh),
// cols 32..63 are tangents u (scale by 1 - h^2). Pairwise independent per (r,m).
__device__ __forceinline__ void act_pass(float* __restrict__ Y, const float* __restrict__ bias, int tid)
{
#pragma unroll 1
    for (int e = tid; e < 256 * TM; e += NTHREADS) {
        int r = e >> 5;
        int m = e & 31;
        float hh = tanhf(Y[r * 64 + m] + bias[r]);
        Y[r * 64 + m] = hh;
        float u = Y[r * 64 + 32 + m];
        Y[r * 64 + 32 + m] = (1.f - hh * hh) * u;
    }
}

__global__ void __launch_bounds__(NTHREADS, 1)
cnf_kernel(const float* __restrict__ x, const float* __restrict__ eps,
           const float* __restrict__ W1, const float* __restrict__ b1,
           const float* __restrict__ W2, const float* __restrict__ b2,
           const float* __restrict__ W3, const float* __restrict__ b3,
           const float* __restrict__ W4, const float* __restrict__ b4,
           float* __restrict__ out)
{
    extern __shared__ float sm[];
    float* bufA = sm;                    // 16384  [256][64]
    float* bufB = bufA + 16384;          // 16384  [256][64]
    float* kdz  = bufB + 16384;          // 12288  [6][64][32]
    float* zb   = kdz + 6 * 64 * TM;     // 2048   [64][32]
    float* ep   = zb + 64 * TM;          // 2048   [64][32]
    float* wp   = ep + 64 * TM;          // 4608   [2][256][9]
    float* kdiv = wp + 2 * 256 * 9;      // 192    [6][32]
    float* red  = kdiv + 6 * TM;         // 256    [8][32]
    float* lpT  = red + 8 * TM;          // 32

    const int tid = threadIdx.x;
    const int mbase = blockIdx.x * TM;

    // load x, eps transposed into shared: [d][m]
    for (int e = tid; e < 64 * TM; e += NTHREADS) {
        int m = e >> 6;
        int d = e & 63;
        zb[d * TM + m] = x[(mbase + m) * 64 + d];
        ep[d * TM + m] = eps[(mbase + m) * 64 + d];
    }
    if (tid < TM) lpT[tid] = 0.f;
    __syncthreads();

#pragma unroll 1
    for (int step = 0; step < 4; step++) {
#pragma unroll 1
        for (int s = 0; s < 6; s++) {
            // Build X: rows 0..63, cols 0..31 = z + h*sum_j a[s][j]*k_j, cols 32..63 = eps
            for (int e = tid; e < 64 * 64; e += NTHREADS) {
                int d = e >> 6;
                int c = e & 63;
                float v;
                if (c < TM) {
                    v = zb[d * TM + c];
                    for (int j = 0; j < s; j++)
                        v += c_HA[s][j] * kdz[(j * 64 + d) * TM + c];
                } else {
                    v = ep[d * TM + (c - TM)];
                }
                bufA[e] = v;
            }
            gemm_layer<256, 64>(W1, bufA, bufB, wp, tid);
            __syncthreads();
            act_pass(bufB, b1, tid);
            gemm_layer<256, 256>(W2, bufB, bufA, wp, tid);
            __syncthreads();
            act_pass(bufA, b2, tid);
            gemm_layer<256, 256>(W3, bufA, bufB, wp, tid);
            __syncthreads();
            act_pass(bufB, b3, tid);
            gemm_layer<64, 256>(W4, bufB, bufA, wp, tid);
            __syncthreads();

            // k_dz (with bias), divergence = sum_d Jeps[d]*eps[d]
            for (int e = tid; e < 64 * TM; e += NTHREADS) {
                int d = e >> 5;
                int m = e & 31;
                kdz[(s * 64 + d) * TM + m] = bufA[d * 64 + m] + b4[d];
            }
            {
                int m = tid & 31;
                int g = tid >> 5;
                float p = 0.f;
#pragma unroll
                for (int dd = 0; dd < 8; dd++) {
                    int d = g * 8 + dd;
                    p += bufA[d * 64 + 32 + m] * ep[d * TM + m];
                }
                red[g * 32 + m] = p;
            }
            __syncthreads();
            if (tid < 32) {
                float dv = 0.f;
#pragma unroll
                for (int g = 0; g < 8; g++) dv += red[g * 32 + tid];
                kdiv[s * 32 + tid] = dv;
            }
            __syncthreads();
        }
        // y_{n+1} = y_n + h*sum b_j k_j   (b[1] == 0)
        for (int e = tid; e < 64 * TM; e += NTHREADS) {
            int d = e >> 5;
            int m = e & 31;
            float v = zb[d * TM + m];
            v += c_HB[0] * kdz[(0 * 64 + d) * TM + m];
            v += c_HB[2] * kdz[(2 * 64 + d) * TM + m];
            v += c_HB[3] * kdz[(3 * 64 + d) * TM + m];
            v += c_HB[4] * kdz[(4 * 64 + d) * TM + m];
            v += c_HB[5] * kdz[(5 * 64 + d) * TM + m];
            zb[d * TM + m] = v;
        }
        if (tid < 32) {
            float dv = c_HB[0] * kdiv[tid]
                     + c_HB[2] * kdiv[2 * 32 + tid]
                     + c_HB[3] * kdiv[3 * 32 + tid]
                     + c_HB[4] * kdiv[4 * 32 + tid]
                     + c_HB[5] * kdiv[5 * 32 + tid];
            lpT[tid] -= dv;   // f's last component is -div
        }
        __syncthreads();
    }

    // out = sum_d(-0.5 z^2 - 0.5 log 2pi) - logpT
    {
        int m = tid & 31;
        int g = tid >> 5;
        float p = 0.f;
#pragma unroll
        for (int dd = 0; dd < 8; dd++) {
            int d = g * 8 + dd;
            float z = zb[d * TM + m];
            p -= 0.5f * z * z;
        }
        red[g * 32 + m] = p;
    }
    __syncthreads();
    if (tid < 32) {
        float sum = 0.f;
#pragma unroll
        for (int g = 0; g < 8; g++) sum += red[g * 32 + tid];
        sum -= 32.f * 1.8378770664093453f;   // 64 * 0.5 * log(2*pi)
        out[mbase + tid] = sum - lpT[tid];
    }
}

extern "C" void kernel_launch(void* const* d_in, const int* in_sizes, int n_in,
                              void* d_out, int out_size)
{
    const float* x   = (const float*)d_in[0];
    const float* eps = (const float*)d_in[1];
    const float* W1  = (const float*)d_in[2];
    const float* b1  = (const float*)d_in[3];
    const float* W2  = (const float*)d_in[4];
    const float* b2  = (const float*)d_in[5];
    const float* W3  = (const float*)d_in[6];
    const float* b3  = (const float*)d_in[7];
    const float* W4  = (const float*)d_in[8];
    const float* b4  = (const float*)d_in[9];
    float* out = (float*)d_out;

    const size_t smem = (size_t)(16384 + 16384 + 6 * 64 * TM + 64 * TM + 64 * TM
                                 + 2 * 256 * 9 + 6 * TM + 8 * TM + TM) * sizeof(float);
    cudaFuncSetAttribute(cnf_kernel, cudaFuncAttributeMaxDynamicSharedMemorySize, (int)smem);
    cnf_kernel<<<32768 / TM, NTHREADS, smem>>>(x, eps, W1, b1, W2, b2, W3, b3, W4, b4, out);
}

// round 2
// speedup vs baseline: 1.0015x; 1.0015x over previous
#include <cuda_runtime.h>

#define TM 32
#define NTHREADS 256

// h * Dormand-Prince A coefficients (h = 1/4)
__constant__ float c_HA[6][5] = {
    {0.f, 0.f, 0.f, 0.f, 0.f},
    {0.05f, 0.f, 0.f, 0.f, 0.f},
    {0.01875f, 0.05625f, 0.f, 0.f, 0.f},
    {0.24444444444444444f, -0.93333333333333333f, 0.88888888888888888f, 0.f, 0.f},
    {0.73814967232162782f, -2.89894833155005335f, 2.45572321290182902f, -0.07270233196159122f, 0.f},
    {0.71156881313131313f, -2.68939393939393939f, 2.22660567943586826f, 0.06960227272727273f, -0.06838282589193830f}
};
// h * b
__constant__ float c_HB[6] = {
    0.02278645833333333f, 0.f, 0.11230907457322552f,
    0.16276041666666666f, -0.08059404481132076f, 0.03273809523809524f
};

// GEMM: Y[ROWS][64] = W[ROWS][K] @ X[K][64], W from global (L2-resident),
// X/Y in shared. Double-buffered W k-panels in shared (wp = 2*256*9 floats).
template<int ROWS, int K>
__device__ __forceinline__ void gemm_layer(
    const float* __restrict__ W,
    const float* __restrict__ X,
    float* __restrict__ Y,
    float* __restrict__ wp,
    int tid)
{
    constexpr int NR = (ROWS == 256) ? 8 : 2;
    const int r0 = (tid >> 3) * NR;
    const int c0 = (tid & 7) * 8;
    float acc[NR][8];
#pragma unroll
    for (int i = 0; i < NR; i++)
#pragma unroll
        for (int j = 0; j < 8; j++) acc[i][j] = 0.f;

    const bool loader = (ROWS == 256) || (tid < 64);
    float4 nv0, nv1;
    if (loader) {
        const float4* src = reinterpret_cast<const float4*>(W + tid * K);
        nv0 = src[0]; nv1 = src[1];
        float* w0 = wp + tid * 9;
        w0[0] = nv0.x; w0[1] = nv0.y; w0[2] = nv0.z; w0[3] = nv0.w;
        w0[4] = nv1.x; w0[5] = nv1.y; w0[6] = nv1.z; w0[7] = nv1.w;
    }
    __syncthreads();
    int buf = 0;
#pragma unroll 1
    for (int kk = 0; kk < K; kk += 8) {
        // prefetch next panel (hidden under compute)
        if (kk + 8 < K && loader) {
            const float4* src = reinterpret_cast<const float4*>(W + tid * K + kk + 8);
            nv0 = src[0]; nv1 = src[1];
        }
        const float* wpb = wp + buf * (256 * 9);
#pragma unroll
        for (int k2 = 0; k2 < 8; k2++) {
            const float* xr = X + (kk + k2) * 64;
            float4 xa = *reinterpret_cast<const float4*>(xr + c0);
            float4 xb = *reinterpret_cast<const float4*>(xr + c0 + 4);
#pragma unroll
            for (int i = 0; i < NR; i++) {
                float w = wpb[(r0 + i) * 9 + k2];
                acc[i][0] += w * xa.x; acc[i][1] += w * xa.y;
                acc[i][2] += w * xa.z; acc[i][3] += w * xa.w;
                acc[i][4] += w * xb.x; acc[i][5] += w * xb.y;
                acc[i][6] += w * xb.z; acc[i][7] += w * xb.w;
            }
        }
        if (kk + 8 < K && loader) {
            float* w1 = wp + (buf ^ 1) * (256 * 9) + tid * 9;
            w1[0] = nv0.x; w1[1] = nv0.y; w1[2] = nv0.z; w1[3] = nv0.w;
            w1[4] = nv1.x; w1[5] = nv1.y; w1[6] = nv1.z; w1[7] = nv1.w;
        }
        __syncthreads();
        buf ^= 1;
    }
#pragma unroll
    for (int i = 0; i < NR; i++) {
        float* yr = Y + (r0 + i) * 64 + c0;
        *reinterpret_cast<float4*>(yr)     = make_float4(acc[i][0], acc[i][1], acc[i][2], acc[i][3]);
        *reinterpret_cast<float4*>(yr + 4) = make_float4(acc[i][4], acc[i][5], acc[i][6], acc[i][7]);
    }
}

// After a hidden-layer GEMM: cols 0..31 are pre-activations (add bias, tanh),
// cols 32..63 are tangents u (scale by 1 - h^2). Pairwise independent per (r,m).
__device__ __forceinline__ void act_pass(float* __restrict__ Y, const float* __restrict__ bias, int tid)
{
#pragma unroll 1
    for (int e = tid; e < 256 * TM; e += NTHREADS) {
        int r = e >> 5;
        int m = e & 31;
        float hh = tanhf(Y[r * 64 + m] + bias[r]);
        Y[r * 64 + m] = hh;
        float u = Y[r * 64 + 32 + m];
        Y[r * 64 + 32 + m] = (1.f - hh * hh) * u;
    }
}

__global__ void __launch_bounds__(NTHREADS, 1)
cnf_kernel(const float* __restrict__ x, const float* __restrict__ eps,
           const float* __restrict__ W1, const float* __restrict__ b1,
           const float* __restrict__ W2, const float* __restrict__ b2,
           const float* __restrict__ W3, const float* __restrict__ b3,
           const float* __restrict__ W4, const float* __restrict__ b4,
           float* __restrict__ out)
{
    extern __shared__ float sm[];
    float* bufA = sm;                    // 16384  [256][64]
    float* bufB = bufA + 16384;          // 16384  [256][64]
    float* kdz  = bufB + 16384;          // 12288  [6][64][32]
    float* zb   = kdz + 6 * 64 * TM;     // 2048   [64][32]
    float* ep   = zb + 64 * TM;          // 2048   [64][32]
    float* wp   = ep + 64 * TM;          // 4608   [2][256][9]
    float* kdiv = wp + 2 * 256 * 9;      // 192    [6][32]
    float* red  = kdiv + 6 * TM;         // 256    [8][32]
    float* lpT  = red + 8 * TM;          // 32

    const int tid = threadIdx.x;
    const int mbase = blockIdx.x * TM;

    // load x, eps transposed into shared: [d][m]
    for (int e = tid; e < 64 * TM; e += NTHREADS) {
        int m = e >> 6;
        int d = e & 63;
        zb[d * TM + m] = x[(mbase + m) * 64 + d];
        ep[d * TM + m] = eps[(mbase + m) * 64 + d];
    }
    if (tid < TM) lpT[tid] = 0.f;
    __syncthreads();

#pragma unroll 1
    for (int step = 0; step < 4; step++) {
#pragma unroll 1
        for (int s = 0; s < 6; s++) {
            // Build X: rows 0..63, cols 0..31 = z + h*sum_j a[s][j]*k_j, cols 32..63 = eps
            for (int e = tid; e < 64 * 64; e += NTHREADS) {
                int d = e >> 6;
                int c = e & 63;
                float v;
                if (c < TM) {
                    v = zb[d * TM + c];
                    for (int j = 0; j < s; j++)
                        v += c_HA[s][j] * kdz[(j * 64 + d) * TM + c];
                } else {
                    v = ep[d * TM + (c - TM)];
                }
                bufA[e] = v;
            }
            gemm_layer<256, 64>(W1, bufA, bufB, wp, tid);
            __syncthreads();
            act_pass(bufB, b1, tid);
            gemm_layer<256, 256>(W2, bufB, bufA, wp, tid);
            __syncthreads();
            act_pass(bufA, b2, tid);
            gemm_layer<256, 256>(W3, bufA, bufB, wp, tid);
            __syncthreads();
            act_pass(bufB, b3, tid);
            gemm_layer<64, 256>(W4, bufB, bufA, wp, tid);
            __syncthreads();

            // k_dz (with bias), divergence = sum_d Jeps[d]*eps[d]
            for (int e = tid; e < 64 * TM; e += NTHREADS) {
                int d = e >> 5;
                int m = e & 31;
                kdz[(s * 64 + d) * TM + m] = bufA[d * 64 + m] + b4[d];
            }
            {
                int m = tid & 31;
                int g = tid >> 5;
                float p = 0.f;
#pragma unroll
                for (int dd = 0; dd < 8; dd++) {
                    int d = g * 8 + dd;
                    p += bufA[d * 64 + 32 + m] * ep[d * TM + m];
                }
                red[g * 32 + m] = p;
            }
            __syncthreads();
            if (tid < 32) {
                float dv = 0.f;
#pragma unroll
                for (int g = 0; g < 8; g++) dv += red[g * 32 + tid];
                kdiv[s * 32 + tid] = dv;
            }
            __syncthreads();
        }
        // y_{n+1} = y_n + h*sum b_j k_j   (b[1] == 0)
        for (int e = tid; e < 64 * TM; e += NTHREADS) {
            int d = e >> 5;
            int m = e & 31;
            float v = zb[d * TM + m];
            v += c_HB[0] * kdz[(0 * 64 + d) * TM + m];
            v += c_HB[2] * kdz[(2 * 64 + d) * TM + m];
            v += c_HB[3] * kdz[(3 * 64 + d) * TM + m];
            v += c_HB[4] * kdz[(4 * 64 + d) * TM + m];
            v += c_HB[5] * kdz[(5 * 64 + d) * TM + m];
            zb[d * TM + m] = v;
        }
        if (tid < 32) {
            float dv = c_HB[0] * kdiv[tid]
                     + c_HB[2] * kdiv[2 * 32 + tid]
                     + c_HB[3] * kdiv[3 * 32 + tid]
                     + c_HB[4] * kdiv[4 * 32 + tid]
                     + c_HB[5] * kdiv[5 * 32 + tid];
            lpT[tid] -= dv;   // f's last component is -div
        }
        __syncthreads();
    }

    // out = sum_d(-0.5 z^2 - 0.5 log 2pi) - logpT
    {
        int m = tid & 31;
        int g = tid >> 5;
        float p = 0.f;
#pragma unroll
        for (int dd = 0; dd < 8; dd++) {
            int d = g * 8 + dd;
            float z = zb[d * TM + m];
            p -= 0.5f * z * z;
        }
        red[g * 32 + m] = p;
    }
    __syncthreads();
    if (tid < 32) {
        float sum = 0.f;
#pragma unroll
        for (int g = 0; g < 8; g++) sum += red[g * 32 + tid];
        sum -= 32.f * 1.8378770664093453f;   // 64 * 0.5 * log(2*pi)
        out[mbase + tid] = sum - lpT[tid];
    }
}

extern "C" void kernel_launch(void* const* d_in, const int* in_sizes, int n_in,
                              void* d_out, int out_size)
{
    const float* x   = (const float*)d_in[0];
    const float* eps = (const float*)d_in[1];
    const float* W1  = (const float*)d_in[2];
    const float* b1  = (const float*)d_in[3];
    const float* W2  = (const float*)d_in[4];
    const float* b2  = (const float*)d_in[5];
    const float* W3  = (const float*)d_in[6];
    const float* b3  = (const float*)d_in[7];
    const float* W4  = (const float*)d_in[8];
    const float* b4  = (const float*)d_in[9];
    float* out = (float*)d_out;

    const size_t smem = (size_t)(16384 + 16384 + 6 * 64 * TM + 64 * TM + 64 * TM
                                 + 2 * 256 * 9 + 6 * TM + 8 * TM + TM) * sizeof(float);
    cudaFuncSetAttribute(cnf_kernel, cudaFuncAttributeMaxDynamicSharedMemorySize, (int)smem);
    cnf_kernel<<<32768 / TM, NTHREADS, smem>>>(x, eps, W1, b1, W2, b2, W3, b3, W4, b4, out);
}

// round 4
// speedup vs baseline: 11.5118x; 11.4942x over previous
#include <cuda_runtime.h>
#include <cuda_fp16.h>
#include <cstdint>

#define NTHREADS 256
#define TM 32

__constant__ float c_HA[6][5] = {
    {0.f, 0.f, 0.f, 0.f, 0.f},
    {0.05f, 0.f, 0.f, 0.f, 0.f},
    {0.01875f, 0.05625f, 0.f, 0.f, 0.f},
    {0.24444444444444444f, -0.93333333333333333f, 0.88888888888888888f, 0.f, 0.f},
    {0.73814967232162782f, -2.89894833155005335f, 2.45572321290182902f, -0.07270233196159122f, 0.f},
    {0.71156881313131313f, -2.68939393939393939f, 2.22660567943586826f, 0.06960227272727273f, -0.06838282589193830f}
};
__constant__ float c_HB[6] = {
    0.02278645833333333f, 0.f, 0.11230907457322552f,
    0.16276041666666666f, -0.08059404481132076f, 0.03273809523809524f
};

// fp16 weights packed in mma fragment order:
// fragment f = (mtile*KSTEPS + kstep); lane l holds 8 halves (one uint4) in
// exact {a0,a1,a2,a3} .f16x2 register order for mma.m16n8k16.
__device__ __align__(16) __half g_Wp1[256 * 64];    //  64 frags
__device__ __align__(16) __half g_Wp2[256 * 256];   // 256 frags
__device__ __align__(16) __half g_Wp3[256 * 256];   // 256 frags
__device__ __align__(16) __half g_Wp4[64 * 256];    //  64 frags

// ---- SMEM byte offsets ----
#define SM_BIAS  0         // 832 floats = 3328 B  (b1|b2|b3|b4)
#define SM_X0    3328      // [64 k][72 halves] = 9216 B
#define SM_XA    12544     // [256][72 halves] = 36864 B
#define SM_XB    49408     // 36864 B
#define SM_KDZ   86272     // [6][64][33] f32 = 50688 B
#define SM_ZB    136960    // [64][33] f32 = 8448 B
#define SM_EP    145408    // 8448 B
#define SM_RED   153856    // [4][32] f32 = 512 B
#define SM_KDIV  154368    // [6][32] f32 = 768 B
#define SM_LPT   155136    // 128 B
#define SM_TOTAL 155264

#define XLD 144            // X row stride in bytes (72 halves) — conflict-free ldmatrix

__device__ __forceinline__ uint32_t smem_u32(const void* p) {
    uint32_t a;
    asm("{ .reg .u64 t; cvta.to.shared.u64 t, %1; cvt.u32.u64 %0, t; }" : "=r"(a) : "l"(p));
    return a;
}
__device__ __forceinline__ void ldsm4t(uint32_t addr, uint32_t& r0, uint32_t& r1,
                                       uint32_t& r2, uint32_t& r3) {
    asm volatile("ldmatrix.sync.aligned.m8n8.x4.trans.shared.b16 {%0,%1,%2,%3}, [%4];"
                 : "=r"(r0), "=r"(r1), "=r"(r2), "=r"(r3) : "r"(addr));
}
__device__ __forceinline__ void mma16816(float* c, const uint4& a, uint32_t b0, uint32_t b1) {
    asm volatile("mma.sync.aligned.m16n8k16.row.col.f32.f16.f16.f32 "
                 "{%0,%1,%2,%3}, {%4,%5,%6,%7}, {%8,%9}, {%0,%1,%2,%3};"
                 : "+f"(c[0]), "+f"(c[1]), "+f"(c[2]), "+f"(c[3])
                 : "r"(a.x), "r"(a.y), "r"(a.z), "r"(a.w), "r"(b0), "r"(b1));
}
// tanh = 1 - 2/(exp(2x)+1) via MUFU ex2/rcp (abs err ~1e-6, 2 MUFU)
__device__ __forceinline__ float tanh_fast(float x) {
    float e, r;
    asm("ex2.approx.f32 %0, %1;" : "=f"(e) : "f"(x * 2.8853900817779268f));
    asm("rcp.approx.f32 %0, %1;" : "=f"(r) : "f"(e + 1.0f));
    return fmaf(-2.0f, r, 1.0f);
}

// ---- prep: pack fp32 weights into fp16 fragment-major layout ----
__global__ void prep_kernel(const float* __restrict__ W1, const float* __restrict__ W2,
                            const float* __restrict__ W3, const float* __restrict__ W4)
{
    int t = blockIdx.x * blockDim.x + threadIdx.x;
    if (t >= 640 * 32) return;
    int frag = t >> 5, lane = t & 31;
    const float* W; __half* dst; int ksn, ld, fl;
    if (frag < 64)       { W = W1; dst = g_Wp1; ksn = 4;  ld = 64;  fl = frag; }
    else if (frag < 320) { W = W2; dst = g_Wp2; ksn = 16; ld = 256; fl = frag - 64; }
    else if (frag < 576) { W = W3; dst = g_Wp3; ksn = 16; ld = 256; fl = frag - 320; }
    else                 { W = W4; dst = g_Wp4; ksn = 16; ld = 256; fl = frag - 576; }
    int mt = fl / ksn, ks = fl % ksn;
    int g = lane >> 2, j2 = (lane & 3) * 2;
    int r0 = mt * 16 + g, r1 = r0 + 8;
    int c0 = ks * 16 + j2;
    __half h[8];
    h[0] = __float2half_rn(W[r0 * ld + c0]);
    h[1] = __float2half_rn(W[r0 * ld + c0 + 1]);
    h[2] = __float2half_rn(W[r1 * ld + c0]);
    h[3] = __float2half_rn(W[r1 * ld + c0 + 1]);
    h[4] = __float2half_rn(W[r0 * ld + c0 + 8]);
    h[5] = __float2half_rn(W[r0 * ld + c0 + 9]);
    h[6] = __float2half_rn(W[r1 * ld + c0 + 8]);
    h[7] = __float2half_rn(W[r1 * ld + c0 + 9]);
    *(uint4*)(dst + fl * 256 + lane * 8) = *(uint4*)h;
}

// ---- tensor-core GEMM: acc[MT][2*NPAIR][4] += Wfrag @ X ----
template<int KSTEPS, int NPAIR, int MT>
__device__ __forceinline__ void gemm_tc(const uint4* __restrict__ wf,
                                        uint32_t xaddr, int lane, float* acc)
{
#pragma unroll
    for (int i = 0; i < MT * NPAIR * 8; i++) acc[i] = 0.f;
    uint4 an[MT];
#pragma unroll
    for (int mt = 0; mt < MT; mt++) an[mt] = wf[mt * KSTEPS * 32 + lane];
#pragma unroll 4
    for (int ks = 0; ks < KSTEPS; ks++) {
        uint4 ac[MT];
#pragma unroll
        for (int mt = 0; mt < MT; mt++) ac[mt] = an[mt];
        if (ks + 1 < KSTEPS) {
#pragma unroll
            for (int mt = 0; mt < MT; mt++) an[mt] = wf[(mt * KSTEPS + ks + 1) * 32 + lane];
        }
        uint32_t b[NPAIR * 2][2];
#pragma unroll
        for (int p = 0; p < NPAIR; p++)
            ldsm4t(xaddr + ks * (16 * XLD) + p * 32,
                   b[2 * p][0], b[2 * p][1], b[2 * p + 1][0], b[2 * p + 1][1]);
#pragma unroll
        for (int mt = 0; mt < MT; mt++)
#pragma unroll
            for (int nb = 0; nb < NPAIR * 2; nb++)
                mma16816(acc + (mt * NPAIR * 2 + nb) * 4, ac[mt], b[nb][0], b[nb][1]);
    }
}

// ---- hidden epilogue: acc(C frag) -> bias+tanh+tangent -> fp16 X tile ----
__device__ __forceinline__ void epi_hidden(const float* acc, char* xout,
                                           const float* bias, int w, int lane)
{
    int g = lane >> 2, j2 = (lane & 3) * 2;
#pragma unroll
    for (int mt = 0; mt < 2; mt++) {
        int r = w * 32 + mt * 16 + g;
        float b0 = bias[r], b8 = bias[r + 8];
        char* row0 = xout + r * XLD;
        char* row8 = row0 + 8 * XLD;
#pragma unroll
        for (int nb = 0; nb < 4; nb++) {
            const float* cf = acc + (mt * 8 + nb) * 4;       // fwd cols nb*8+j2
            const float* ct = acc + (mt * 8 + nb + 4) * 4;   // tangent cols +32
            int n2 = (nb * 8 + j2) * 2;
            float y0 = tanh_fast(cf[0] + b0), y1 = tanh_fast(cf[1] + b0);
            *(__half2*)(row0 + n2)      = __floats2half2_rn(y0, y1);
            *(__half2*)(row0 + 64 + n2) = __floats2half2_rn((1.f - y0 * y0) * ct[0],
                                                            (1.f - y1 * y1) * ct[1]);
            float y2 = tanh_fast(cf[2] + b8), y3 = tanh_fast(cf[3] + b8);
            *(__half2*)(row8 + n2)      = __floats2half2_rn(y2, y3);
            *(__half2*)(row8 + 64 + n2) = __floats2half2_rn((1.f - y2 * y2) * ct[2],
                                                            (1.f - y3 * y3) * ct[3]);
        }
    }
}

__global__ void __launch_bounds__(NTHREADS, 1)
cnf_kernel(const float* __restrict__ x, const float* __restrict__ eps,
           const float* __restrict__ b1, const float* __restrict__ b2,
           const float* __restrict__ b3, const float* __restrict__ b4,
           float* __restrict__ out)
{
    extern __shared__ char smc[];
    const uint32_t sbase = smem_u32(smc);
    const int tid = threadIdx.x;
    const int w = tid >> 5;
    const int lane = tid & 31;
    const int mbase = blockIdx.x * TM;

    float* bias = (float*)(smc + SM_BIAS);
    char*  x0s  = smc + SM_X0;
    char*  xas  = smc + SM_XA;
    char*  xbs  = smc + SM_XB;
    float* kdz  = (float*)(smc + SM_KDZ);
    float* zb   = (float*)(smc + SM_ZB);
    float* ep   = (float*)(smc + SM_EP);
    float* red  = (float*)(smc + SM_RED);
    float* kdiv = (float*)(smc + SM_KDIV);
    float* lpT  = (float*)(smc + SM_LPT);
    const float* b4s = bias + 768;

    // biases
    bias[tid]       = b1[tid];
    bias[256 + tid] = b2[tid];
    bias[512 + tid] = b3[tid];
    if (tid < 64) bias[768 + tid] = b4[tid];
    // state (transposed) + X0 tangent half (= eps, constant across stages)
    for (int e = tid; e < 64 * TM; e += NTHREADS) {
        int d = e & 63, m = e >> 6;
        float xv = x[(mbase + m) * 64 + d];
        float ev = eps[(mbase + m) * 64 + d];
        zb[d * 33 + m] = xv;
        ep[d * 33 + m] = ev;
        *(__half*)(x0s + d * XLD + (32 + m) * 2) = __float2half_rn(ev);
    }
    if (tid < TM) lpT[tid] = 0.f;
    __syncthreads();

    // per-lane ldmatrix address pattern: row k = (l&7)+8*((l>>3)&1), +8 cols for l>=16
    const uint32_t xpat = ((lane & 7) + ((lane >> 3) & 1) * 8) * XLD + (lane >> 4) * 16;
    float acc[64];

#pragma unroll 1
    for (int step = 0; step < 4; step++) {
#pragma unroll 1
        for (int s = 0; s < 6; s++) {
            // prologue: X0 fwd cols = z + h*sum a[s][j]*k_j (fp16)
            for (int e = tid; e < 64 * 16; e += NTHREADS) {
                int d = e >> 4, mp = (e & 15) * 2;
                float v0 = zb[d * 33 + mp], v1 = zb[d * 33 + mp + 1];
                for (int j = 0; j < s; j++) {
                    float a = c_HA[s][j];
                    v0 += a * kdz[(j * 64 + d) * 33 + mp];
                    v1 += a * kdz[(j * 64 + d) * 33 + mp + 1];
                }
                *(__half2*)(x0s + d * XLD + mp * 2) = __floats2half2_rn(v0, v1);
            }
            __syncthreads();

            // L1: 256x64 @ K=64
            gemm_tc<4, 4, 2>((const uint4*)g_Wp1 + (w * 2 * 4) * 32,
                             sbase + SM_X0 + xpat, lane, acc);
            epi_hidden(acc, xas, bias, w, lane);
            __syncthreads();
            // L2: 256x64 @ K=256
            gemm_tc<16, 4, 2>((const uint4*)g_Wp2 + (w * 2 * 16) * 32,
                              sbase + SM_XA + xpat, lane, acc);
            epi_hidden(acc, xbs, bias + 256, w, lane);
            __syncthreads();
            // L3
            gemm_tc<16, 4, 2>((const uint4*)g_Wp3 + (w * 2 * 16) * 32,
                              sbase + SM_XB + xpat, lane, acc);
            epi_hidden(acc, xas, bias + 512, w, lane);
            __syncthreads();
            // L4: 64x64 @ K=256 — warp w: mtile=w>>1, n-half=w&1
            gemm_tc<16, 2, 1>((const uint4*)g_Wp4 + ((w >> 1) * 16) * 32,
                              sbase + SM_XA + (w & 1) * 64 + xpat, lane, acc);
            {
                int g = lane >> 2, j2 = (lane & 3) * 2;
                int mtile = w >> 1;
                int d0 = mtile * 16 + g;
                if ((w & 1) == 0) {
                    // fwd half: kdz = D + b4
#pragma unroll
                    for (int nb = 0; nb < 4; nb++) {
                        const float* c = acc + nb * 4;
                        int m = nb * 8 + j2;
                        kdz[(s * 64 + d0) * 33 + m]         = c[0] + b4s[d0];
                        kdz[(s * 64 + d0) * 33 + m + 1]     = c[1] + b4s[d0];
                        kdz[(s * 64 + d0 + 8) * 33 + m]     = c[2] + b4s[d0 + 8];
                        kdz[(s * 64 + d0 + 8) * 33 + m + 1] = c[3] + b4s[d0 + 8];
                    }
                } else {
                    // tangent half: partial divergence over this mtile's 16 dims
                    float s0[4], s1[4];
#pragma unroll
                    for (int nb = 0; nb < 4; nb++) {
                        const float* c = acc + nb * 4;
                        int m = nb * 8 + j2;
                        s0[nb] = c[0] * ep[d0 * 33 + m]     + c[2] * ep[(d0 + 8) * 33 + m];
                        s1[nb] = c[1] * ep[d0 * 33 + m + 1] + c[3] * ep[(d0 + 8) * 33 + m + 1];
                    }
#pragma unroll
                    for (int mask = 4; mask <= 16; mask <<= 1) {
#pragma unroll
                        for (int nb = 0; nb < 4; nb++) {
                            s0[nb] += __shfl_xor_sync(0xffffffffu, s0[nb], mask);
                            s1[nb] += __shfl_xor_sync(0xffffffffu, s1[nb], mask);
                        }
                    }
                    if (g == 0) {
#pragma unroll
                        for (int nb = 0; nb < 4; nb++) {
                            int m = nb * 8 + j2;
                            red[mtile * 32 + m]     = s0[nb];
                            red[mtile * 32 + m + 1] = s1[nb];
                        }
                    }
                }
            }
            __syncthreads();
            if (tid < 32)
                kdiv[s * 32 + tid] = red[tid] + red[32 + tid] + red[64 + tid] + red[96 + tid];
            __syncthreads();
        }
        // RK45 combine (b[1] == 0)
        for (int e = tid; e < 64 * TM; e += NTHREADS) {
            int m = e & 31, d = e >> 5;
            float v = zb[d * 33 + m];
            v += c_HB[0] * kdz[(0 * 64 + d) * 33 + m];
            v += c_HB[2] * kdz[(2 * 64 + d) * 33 + m];
            v += c_HB[3] * kdz[(3 * 64 + d) * 33 + m];
            v += c_HB[4] * kdz[(4 * 64 + d) * 33 + m];
            v += c_HB[5] * kdz[(5 * 64 + d) * 33 + m];
            zb[d * 33 + m] = v;
        }
        if (tid < 32) {
            float dv = c_HB[0] * kdiv[tid]
                     + c_HB[2] * kdiv[2 * 32 + tid]
                     + c_HB[3] * kdiv[3 * 32 + tid]
                     + c_HB[4] * kdiv[4 * 32 + tid]
                     + c_HB[5] * kdiv[5 * 32 + tid];
            lpT[tid] -= dv;
        }
        __syncthreads();
    }

    // out = sum_d(-0.5 z^2) - 32*log(2pi) - logpT
    {
        int m = tid & 31, g = tid >> 5;
        float p = 0.f;
#pragma unroll
        for (int dd = 0; dd < 8; dd++) {
            float z = zb[(g * 8 + dd) * 33 + m];
            p -= 0.5f * z * z;
        }
        red[0] = red[0]; // keep red live
        ((float*)(smc + SM_RED))[g * 32 + m] = p;
    }
    __syncthreads();
    if (tid < 32) {
        float sum = 0.f;
        const float* rr = (const float*)(smc + SM_RED);
#pragma unroll
        for (int g = 0; g < 8; g++) sum += rr[g * 32 + tid];
        sum -= 32.f * 1.8378770664093453f;
        out[mbase + tid] = sum - lpT[tid];
    }
}

extern "C" void kernel_launch(void* const* d_in, const int* in_sizes, int n_in,
                              void* d_out, int out_size)
{
    const float* x   = (const float*)d_in[0];
    const float* eps = (const float*)d_in[1];
    const float* W1  = (const float*)d_in[2];
    const float* b1  = (const float*)d_in[3];
    const float* W2  = (const float*)d_in[4];
    const float* b2  = (const float*)d_in[5];
    const float* W3  = (const float*)d_in[6];
    const float* b3  = (const float*)d_in[7];
    const float* W4  = (const float*)d_in[8];
    const float* b4  = (const float*)d_in[9];
    float* out = (float*)d_out;

    prep_kernel<<<(640 * 32 + 255) / 256, 256>>>(W1, W2, W3, W4);

    cudaFuncSetAttribute(cnf_kernel, cudaFuncAttributeMaxDynamicSharedMemorySize, SM_TOTAL);
    cnf_kernel<<<32768 / TM, NTHREADS, SM_TOTAL>>>(x, eps, b1, b2, b3, b4, out);
}